// round 1
// baseline (speedup 1.0000x reference)
#include <cuda_runtime.h>
#include <math.h>

#define BATCH 32
#define NHEADS 8
#define HD 64
#define HID 512
#define MLEN 8192
#define NTOT 256   // BATCH*NHEADS

// scratch (static device globals — no runtime allocation)
__device__ float g_q[NTOT * HD];          // q projected, pre-scaled by 1/8
__device__ float g_pe[NTOT * MLEN];       // positional score term, 8 MB
__device__ float g_ctx[BATCH * HID];      // attention context before Wo

// ---------------------------------------------------------------------------
// Kernel 1: q projection.  q[b][o] = (query[b] . Wq[o]) * 0.125
// grid = BATCH blocks, 512 threads
// ---------------------------------------------------------------------------
__global__ void qproj_kernel(const float* __restrict__ query,
                             const float* __restrict__ Wq) {
    __shared__ float x[HID];
    int b = blockIdx.x;
    x[threadIdx.x] = query[b * HID + threadIdx.x];
    __syncthreads();
    int o = threadIdx.x;
    const float4* wrow = reinterpret_cast<const float4*>(Wq + (size_t)o * HID);
    float acc = 0.f;
#pragma unroll 8
    for (int k = 0; k < HID / 4; k++) {
        float4 wv = wrow[k];
        acc += wv.x * x[4 * k] + wv.y * x[4 * k + 1] +
               wv.z * x[4 * k + 2] + wv.w * x[4 * k + 3];
    }
    // layout: [b][h*64+d] flat == [n][d] flat
    g_q[b * HID + o] = acc * 0.125f;   // fold 1/sqrt(64) into q
}

// ---------------------------------------------------------------------------
// Kernel 2: positional score GEMM.  pe_s[n][m] = sum_d q[n][d] * key_pe[d][m]
// C[256,8192] = A[256,64] x B[64,8192].  Block tile 64n x 64m, thread 4x4.
// grid = (128, 4), 256 threads
// ---------------------------------------------------------------------------
__global__ void pe_kernel(const float* __restrict__ key_pe) {
    __shared__ float qT[64][68];   // [d][n], padded
    __shared__ float pT[64][68];   // [d][m], padded
    int m0 = blockIdx.x * 64;
    int n0 = blockIdx.y * 64;
    int t = threadIdx.x;
#pragma unroll
    for (int j = 0; j < 16; j++) {
        int idx = t + 256 * j;
        int a = idx & 63;          // fast-varying within warp
        int c = idx >> 6;
        // pT: a = m (coalesced gmem read, conflict-free smem write)
        pT[c][a] = key_pe[c * MLEN + m0 + a];
        // qT: a = d (coalesced gmem read); smem write has small conflicts, ok
        qT[a][c] = g_q[(n0 + c) * HD + a];
    }
    __syncthreads();
    int tx = t & 15, ty = t >> 4;
    float acc[4][4];
#pragma unroll
    for (int i = 0; i < 4; i++)
#pragma unroll
        for (int j = 0; j < 4; j++) acc[i][j] = 0.f;

#pragma unroll 4
    for (int d = 0; d < 64; d++) {
        float4 a4 = *reinterpret_cast<float4*>(&qT[d][ty * 4]);
        float4 b4 = *reinterpret_cast<float4*>(&pT[d][tx * 4]);
        float av[4] = {a4.x, a4.y, a4.z, a4.w};
        float bv[4] = {b4.x, b4.y, b4.z, b4.w};
#pragma unroll
        for (int i = 0; i < 4; i++)
#pragma unroll
            for (int j = 0; j < 4; j++) acc[i][j] = fmaf(av[i], bv[j], acc[i][j]);
    }
#pragma unroll
    for (int i = 0; i < 4; i++) {
        float4 r = make_float4(acc[i][0], acc[i][1], acc[i][2], acc[i][3]);
        *reinterpret_cast<float4*>(
            &g_pe[(size_t)(n0 + ty * 4 + i) * MLEN + m0 + tx * 4]) = r;
    }
}

// ---------------------------------------------------------------------------
// Kernel 3: main attention.  One CTA per n = b*8+h.  256 threads = 8 warps.
// Phase 1: scores -> smem (stream key, 512 MB total)
// Phase 2: exact softmax + adaptive-span mask + renorm sums
// Phase 3: weighted value sum (stream value, 512 MB total)
// ---------------------------------------------------------------------------
__global__ __launch_bounds__(256) void attn_kernel(const float* __restrict__ key,
                                                   const float* __restrict__ value,
                                                   const float* __restrict__ span) {
    __shared__ float s_sm[MLEN];   // 32 KB: scores, then weights
    __shared__ float red[512];
    __shared__ float wred[16];

    int n = blockIdx.x;
    int t = threadIdx.x, w = t >> 5, lane = t & 31;
    int sl = lane & 15, half = lane >> 4;

    const float* krow = key + (size_t)n * MLEN * HD;
    const float* pen = &g_pe[(size_t)n * MLEN];
    float4 q4 = *reinterpret_cast<const float4*>(&g_q[n * HD + 4 * sl]);

    // ---- Phase 1: scores. Warp handles 2 rows per step (16-lane split),
    // each lane loads float4 of a key row (warp: 512 B coalesced).
    float lmax = -1e30f;
#pragma unroll 4
    for (int i = 0; i < MLEN / 16; i++) {
        int m = i * 16 + w * 2 + half;
        float4 k4 = *(reinterpret_cast<const float4*>(krow + (size_t)m * HD) + sl);
        float p = q4.x * k4.x + q4.y * k4.y + q4.z * k4.z + q4.w * k4.w;
        p += __shfl_xor_sync(0xffffffffu, p, 8);
        p += __shfl_xor_sync(0xffffffffu, p, 4);
        p += __shfl_xor_sync(0xffffffffu, p, 2);
        p += __shfl_xor_sync(0xffffffffu, p, 1);
        float p1 = __shfl_sync(0xffffffffu, p, 16);  // half-1 row sum
        if (lane == 0) {
            int mb = i * 16 + w * 2;
            float2 pe2 = *reinterpret_cast<const float2*>(pen + mb);
            float s0 = pe2.x + p;
            float s1 = pe2.y + p1;
            *reinterpret_cast<float2*>(&s_sm[mb]) = make_float2(s0, s1);
            lmax = fmaxf(lmax, fmaxf(s0, s1));
        }
    }
    if (lane == 0) wred[w] = lmax;
    __syncthreads();
    float bmax = wred[0];
#pragma unroll
    for (int j = 1; j < 8; j++) bmax = fmaxf(bmax, wred[j]);

    // ---- Phase 2: exp, mask, sums.  p[m] = e[m]*mask[m]/(Zm + 1e-8*Z)
    float spanM = span[n & (NHEADS - 1)] * (float)MLEN;
    float z = 0.f, zm = 0.f;
#pragma unroll 4
    for (int m = t; m < MLEN; m += 256) {
        float e = __expf(s_sm[m] - bmax);
        float mk = ((float)(m + 1 - MLEN) + spanM) * (1.0f / 32.0f) + 1.0f;
        mk = fminf(fmaxf(mk, 0.f), 1.f);
        float em = e * mk;
        z += e;
        zm += em;
        s_sm[m] = em;
    }
#pragma unroll
    for (int off = 16; off > 0; off >>= 1) {
        z += __shfl_xor_sync(0xffffffffu, z, off);
        zm += __shfl_xor_sync(0xffffffffu, zm, off);
    }
    if (lane == 0) { red[w] = z; red[8 + w] = zm; }
    __syncthreads();
    float zt = 0.f, zmt = 0.f;
#pragma unroll
    for (int j = 0; j < 8; j++) { zt += red[j]; zmt += red[8 + j]; }
    float inv = 1.0f / (zmt + 1e-8f * zt);
    __syncthreads();   // red about to be reused; s_sm weights now final

    // ---- Phase 3: o[d] = sum_m w[m] * v[m][d].  Warp owns all 64 dims
    // (float2/lane), strides over m (warp load = 256 B coalesced).
    float2 acc = make_float2(0.f, 0.f);
    const float2* vb = reinterpret_cast<const float2*>(value + (size_t)n * MLEN * HD) + lane;
#pragma unroll 4
    for (int m = w; m < MLEN; m += 8) {
        float wv = s_sm[m];
        float2 v = vb[(size_t)m * 32];
        acc.x = fmaf(wv, v.x, acc.x);
        acc.y = fmaf(wv, v.y, acc.y);
    }
    *reinterpret_cast<float2*>(&red[w * 64 + 2 * lane]) = acc;
    __syncthreads();
    if (t < 64) {
        float s = 0.f;
#pragma unroll
        for (int j = 0; j < 8; j++) s += red[j * 64 + t];
        g_ctx[n * HD + t] = s * inv;   // n*64+d == b*512 + h*64 + d
    }
}

// ---------------------------------------------------------------------------
// Kernel 4: output projection.  out[b][o] = ctx[b] . Wo[o]
// ---------------------------------------------------------------------------
__global__ void oproj_kernel(const float* __restrict__ Wo,
                             float* __restrict__ out) {
    __shared__ float x[HID];
    int b = blockIdx.x;
    x[threadIdx.x] = g_ctx[b * HID + threadIdx.x];
    __syncthreads();
    int o = threadIdx.x;
    const float4* wrow = reinterpret_cast<const float4*>(Wo + (size_t)o * HID);
    float acc = 0.f;
#pragma unroll 8
    for (int k = 0; k < HID / 4; k++) {
        float4 wv = wrow[k];
        acc += wv.x * x[4 * k] + wv.y * x[4 * k + 1] +
               wv.z * x[4 * k + 2] + wv.w * x[4 * k + 3];
    }
    out[b * HID + o] = acc;
}

// ---------------------------------------------------------------------------
extern "C" void kernel_launch(void* const* d_in, const int* in_sizes, int n_in,
                              void* d_out, int out_size) {
    const float* query  = (const float*)d_in[0];
    const float* key    = (const float*)d_in[1];
    const float* value  = (const float*)d_in[2];
    const float* Wq     = (const float*)d_in[3];
    const float* Wo     = (const float*)d_in[4];
    const float* key_pe = (const float*)d_in[5];
    const float* span   = (const float*)d_in[6];
    float* out = (float*)d_out;
    (void)in_sizes; (void)n_in; (void)out_size;

    qproj_kernel<<<BATCH, HID>>>(query, Wq);
    pe_kernel<<<dim3(MLEN / 64, NTOT / 64), 256>>>(key_pe);
    attn_kernel<<<NTOT, 256>>>(key, value, span);
    oproj_kernel<<<BATCH, HID>>>(Wo, out);
}

// round 2
// speedup vs baseline: 2.1603x; 2.1603x over previous
#include <cuda_runtime.h>
#include <math.h>

#define BATCH 32
#define NHEADS 8
#define HD 64
#define HID 512
#define MLEN 8192
#define NTOT 256          // BATCH*NHEADS
#define SPLIT 8
#define CHUNK (MLEN / SPLIT)   // 1024

// scratch (static device globals — no runtime allocation)
__device__ float g_q[NTOT * HD];               // q projected, pre-scaled by 1/8
__device__ float g_pe[NTOT * MLEN];            // positional score term, 8 MB
__device__ float g_ctx[BATCH * HID];           // attention context before Wo
__device__ float g_pmax[NTOT * SPLIT];         // per-split local max
__device__ float g_pz[NTOT * SPLIT];           // per-split sum e
__device__ float g_pzm[NTOT * SPLIT];          // per-split sum e*mask
__device__ float g_pout[NTOT * SPLIT * HD];    // per-split partial output

// ---------------------------------------------------------------------------
// GEMV helper pattern: block = 512 threads (16 warps), grid (B, 4).
// Each warp computes 8 outputs; per output the warp does 4 coalesced
// float4 loads (512B/step) of the weight row + smem x, shfl-reduce.
// ---------------------------------------------------------------------------
__global__ __launch_bounds__(512) void qproj_kernel(const float* __restrict__ query,
                                                    const float* __restrict__ Wq) {
    __shared__ float xs[HID];
    int b = blockIdx.x;
    xs[threadIdx.x] = query[b * HID + threadIdx.x];
    __syncthreads();
    const float4* xs4 = reinterpret_cast<const float4*>(xs);
    int w = threadIdx.x >> 5, lane = threadIdx.x & 31;
#pragma unroll
    for (int j = 0; j < 8; j++) {
        int o = blockIdx.y * 128 + w * 8 + j;
        const float4* wr = reinterpret_cast<const float4*>(Wq + (size_t)o * HID);
        float acc = 0.f;
#pragma unroll
        for (int s = 0; s < 4; s++) {
            float4 wv = wr[lane + 32 * s];
            float4 xv = xs4[lane + 32 * s];
            acc += wv.x * xv.x + wv.y * xv.y + wv.z * xv.z + wv.w * xv.w;
        }
#pragma unroll
        for (int off = 16; off > 0; off >>= 1)
            acc += __shfl_xor_sync(0xffffffffu, acc, off);
        if (lane == 0) g_q[b * HID + o] = acc * 0.125f;  // fold 1/sqrt(64)
    }
}

// ---------------------------------------------------------------------------
// Kernel 2: positional score GEMM.  pe_s[n][m] = sum_d q[n][d] * key_pe[d][m]
// C[256,8192] = A[256,64] x B[64,8192].  Block tile 64n x 64m, thread 4x4.
// ---------------------------------------------------------------------------
__global__ void pe_kernel(const float* __restrict__ key_pe) {
    __shared__ float qT[64][68];   // [d][n], padded
    __shared__ float pT[64][68];   // [d][m], padded
    int m0 = blockIdx.x * 64;
    int n0 = blockIdx.y * 64;
    int t = threadIdx.x;
#pragma unroll
    for (int j = 0; j < 16; j++) {
        int idx = t + 256 * j;
        int a = idx & 63;
        int c = idx >> 6;
        pT[c][a] = key_pe[c * MLEN + m0 + a];
        qT[a][c] = g_q[(n0 + c) * HD + a];
    }
    __syncthreads();
    int tx = t & 15, ty = t >> 4;
    float acc[4][4];
#pragma unroll
    for (int i = 0; i < 4; i++)
#pragma unroll
        for (int j = 0; j < 4; j++) acc[i][j] = 0.f;

#pragma unroll 4
    for (int d = 0; d < 64; d++) {
        float4 a4 = *reinterpret_cast<float4*>(&qT[d][ty * 4]);
        float4 b4 = *reinterpret_cast<float4*>(&pT[d][tx * 4]);
        float av[4] = {a4.x, a4.y, a4.z, a4.w};
        float bv[4] = {b4.x, b4.y, b4.z, b4.w};
#pragma unroll
        for (int i = 0; i < 4; i++)
#pragma unroll
            for (int j = 0; j < 4; j++) acc[i][j] = fmaf(av[i], bv[j], acc[i][j]);
    }
#pragma unroll
    for (int i = 0; i < 4; i++) {
        float4 r = make_float4(acc[i][0], acc[i][1], acc[i][2], acc[i][3]);
        *reinterpret_cast<float4*>(
            &g_pe[(size_t)(n0 + ty * 4 + i) * MLEN + m0 + tx * 4]) = r;
    }
}

// ---------------------------------------------------------------------------
// Kernel 3: split attention.  grid (SPLIT, NTOT), 256 threads.
// Each CTA handles m in [split*CHUNK, (split+1)*CHUNK) for one n.
// Emits partial (lmax, z, zm, out[64]) in local-max scale.
// Value reads are skipped where the span mask is exactly zero.
// ---------------------------------------------------------------------------
__global__ __launch_bounds__(256) void attn_split_kernel(const float* __restrict__ key,
                                                         const float* __restrict__ value,
                                                         const float* __restrict__ span) {
    __shared__ float s_sm[CHUNK];   // 4 KB: scores, then weights e*mask
    __shared__ float red[512];
    __shared__ float wred[16];

    int split = blockIdx.x;
    int n = blockIdx.y;
    int m0 = split * CHUNK;
    int t = threadIdx.x, w = t >> 5, lane = t & 31;
    int sl = lane & 15, half = lane >> 4;

    const float* krow = key + (size_t)n * MLEN * HD + (size_t)m0 * HD;
    const float* pen = &g_pe[(size_t)n * MLEN + m0];
    float4 q4 = *reinterpret_cast<const float4*>(&g_q[n * HD + 4 * sl]);

    // ---- Phase 1: scores. Warp does 2 rows per step (16-lane split);
    // warp load = 512B contiguous.
    float lmax = -1e30f;
#pragma unroll 4
    for (int i = 0; i < CHUNK / 16; i++) {
        int m = i * 16 + w * 2 + half;
        float4 k4 = *(reinterpret_cast<const float4*>(krow + (size_t)m * HD) + sl);
        float p = q4.x * k4.x + q4.y * k4.y + q4.z * k4.z + q4.w * k4.w;
        p += __shfl_xor_sync(0xffffffffu, p, 8);
        p += __shfl_xor_sync(0xffffffffu, p, 4);
        p += __shfl_xor_sync(0xffffffffu, p, 2);
        p += __shfl_xor_sync(0xffffffffu, p, 1);
        float p1 = __shfl_sync(0xffffffffu, p, 16);
        if (lane == 0) {
            int mb = i * 16 + w * 2;
            float2 pe2 = *reinterpret_cast<const float2*>(pen + mb);
            float s0 = pe2.x + p;
            float s1 = pe2.y + p1;
            *reinterpret_cast<float2*>(&s_sm[mb]) = make_float2(s0, s1);
            lmax = fmaxf(lmax, fmaxf(s0, s1));
        }
    }
    if (lane == 0) wred[w] = lmax;
    __syncthreads();
    float bmax = wred[0];
#pragma unroll
    for (int j = 1; j < 8; j++) bmax = fmaxf(bmax, wred[j]);

    // ---- Phase 2: exp, mask, partial sums (local-max scale).
    float spanM = span[n & (NHEADS - 1)] * (float)MLEN;
    float z = 0.f, zm = 0.f;
#pragma unroll 4
    for (int ml = t; ml < CHUNK; ml += 256) {
        int m = m0 + ml;
        float e = __expf(s_sm[ml] - bmax);
        float mk = ((float)(m + 1 - MLEN) + spanM) * (1.0f / 32.0f) + 1.0f;
        mk = fminf(fmaxf(mk, 0.f), 1.f);
        float em = e * mk;
        z += e;
        zm += em;
        s_sm[ml] = em;
    }
#pragma unroll
    for (int off = 16; off > 0; off >>= 1) {
        z += __shfl_xor_sync(0xffffffffu, z, off);
        zm += __shfl_xor_sync(0xffffffffu, zm, off);
    }
    if (lane == 0) { red[w] = z; red[8 + w] = zm; }
    __syncthreads();
    float zt = 0.f, zmt = 0.f;
#pragma unroll
    for (int j = 0; j < 8; j++) { zt += red[j]; zmt += red[8 + j]; }
    __syncthreads();   // red reused below; s_sm weights final

    // ---- Phase 3: partial out over visible m only.
    // Mask is exactly 0 for m <= MLEN-33-spanM; conservative start (stored
    // weights in the margin are exact zeros, so result is bit-exact).
    int ms = (int)floorf((float)(MLEN - 33) - spanM) - 2;
    int base = ms - m0;
    if (base < 0) base = 0;
    base &= ~7;

    float2 acc = make_float2(0.f, 0.f);
    if (base < CHUNK) {
        const float2* vb =
            reinterpret_cast<const float2*>(value + (size_t)n * MLEN * HD +
                                            (size_t)m0 * HD) + lane;
#pragma unroll 4
        for (int ml = base + w; ml < CHUNK; ml += 8) {
            float wv = s_sm[ml];
            float2 v = vb[(size_t)ml * 32];
            acc.x = fmaf(wv, v.x, acc.x);
            acc.y = fmaf(wv, v.y, acc.y);
        }
    }
    *reinterpret_cast<float2*>(&red[w * 64 + 2 * lane]) = acc;
    __syncthreads();
    int ps = n * SPLIT + split;
    if (t < 64) {
        float s = 0.f;
#pragma unroll
        for (int j = 0; j < 8; j++) s += red[j * 64 + t];
        g_pout[(size_t)ps * HD + t] = s;
    }
    if (t == 64) { g_pmax[ps] = bmax; g_pz[ps] = zt; g_pzm[ps] = zmt; }
}

// ---------------------------------------------------------------------------
// Kernel 4: combine splits.  grid NTOT, 64 threads.
// ---------------------------------------------------------------------------
__global__ __launch_bounds__(64) void combine_kernel() {
    int n = blockIdx.x;
    int d = threadIdx.x;
    float lm[SPLIT];
    float gmax = -1e30f;
#pragma unroll
    for (int i = 0; i < SPLIT; i++) {
        lm[i] = g_pmax[n * SPLIT + i];
        gmax = fmaxf(gmax, lm[i]);
    }
    float Z = 0.f, Zm = 0.f, o = 0.f;
#pragma unroll
    for (int i = 0; i < SPLIT; i++) {
        float c = __expf(lm[i] - gmax);
        Z = fmaf(c, g_pz[n * SPLIT + i], Z);
        Zm = fmaf(c, g_pzm[n * SPLIT + i], Zm);
        o = fmaf(c, g_pout[(size_t)(n * SPLIT + i) * HD + d], o);
    }
    g_ctx[n * HD + d] = o / (Zm + 1e-8f * Z);
}

// ---------------------------------------------------------------------------
// Kernel 5: output projection (same warp-per-output GEMV as qproj).
// ---------------------------------------------------------------------------
__global__ __launch_bounds__(512) void oproj_kernel(const float* __restrict__ Wo,
                                                    float* __restrict__ out) {
    __shared__ float xs[HID];
    int b = blockIdx.x;
    xs[threadIdx.x] = g_ctx[b * HID + threadIdx.x];
    __syncthreads();
    const float4* xs4 = reinterpret_cast<const float4*>(xs);
    int w = threadIdx.x >> 5, lane = threadIdx.x & 31;
#pragma unroll
    for (int j = 0; j < 8; j++) {
        int o = blockIdx.y * 128 + w * 8 + j;
        const float4* wr = reinterpret_cast<const float4*>(Wo + (size_t)o * HID);
        float acc = 0.f;
#pragma unroll
        for (int s = 0; s < 4; s++) {
            float4 wv = wr[lane + 32 * s];
            float4 xv = xs4[lane + 32 * s];
            acc += wv.x * xv.x + wv.y * xv.y + wv.z * xv.z + wv.w * xv.w;
        }
#pragma unroll
        for (int off = 16; off > 0; off >>= 1)
            acc += __shfl_xor_sync(0xffffffffu, acc, off);
        if (lane == 0) out[b * HID + o] = acc;
    }
}

// ---------------------------------------------------------------------------
extern "C" void kernel_launch(void* const* d_in, const int* in_sizes, int n_in,
                              void* d_out, int out_size) {
    const float* query  = (const float*)d_in[0];
    const float* key    = (const float*)d_in[1];
    const float* value  = (const float*)d_in[2];
    const float* Wq     = (const float*)d_in[3];
    const float* Wo     = (const float*)d_in[4];
    const float* key_pe = (const float*)d_in[5];
    const float* span   = (const float*)d_in[6];
    float* out = (float*)d_out;
    (void)in_sizes; (void)n_in; (void)out_size;

    qproj_kernel<<<dim3(BATCH, 4), 512>>>(query, Wq);
    pe_kernel<<<dim3(MLEN / 64, NTOT / 64), 256>>>(key_pe);
    attn_split_kernel<<<dim3(SPLIT, NTOT), 256>>>(key, value, span);
    combine_kernel<<<NTOT, 64>>>();
    oproj_kernel<<<dim3(BATCH, 4), 512>>>(Wo, out);
}

// round 3
// speedup vs baseline: 2.3822x; 1.1027x over previous
#include <cuda_runtime.h>
#include <math.h>

#define BATCH 32
#define NHEADS 8
#define HD 64
#define HID 512
#define MLEN 8192
#define NTOT 256          // BATCH*NHEADS
#define SPLIT 8
#define MAXCHUNK 1024     // ceil(MLEN/SPLIT) rounded to 16

// scratch (static device globals — no runtime allocation)
__device__ float g_q[NTOT * HD];               // q projected, pre-scaled by 1/8
__device__ float g_pe[NTOT * MLEN];            // positional score term
__device__ float g_pmax[NTOT * SPLIT];         // per-split local max
__device__ float g_pz[NTOT * SPLIT];           // per-split sum e
__device__ float g_pzm[NTOT * SPLIT];          // per-split sum e*mask
__device__ float g_pout[NTOT * SPLIT * HD];    // per-split partial output

// visible-window start for one head's span (mask == 0 for m <= M-33-spanM;
// -2 margin keeps it bit-safe against float rounding)
__device__ __forceinline__ int vis_start(float spanM) {
    int ms = (int)floorf((float)(MLEN - 33) - spanM) - 2;
    return ms < 0 ? 0 : ms;
}

// ---------------------------------------------------------------------------
// Kernel 1: q projection.  grid (BATCH, 4), 512 threads.
// Warp computes 8 outputs; coalesced 512B weight-row loads + shfl reduce.
// ---------------------------------------------------------------------------
__global__ __launch_bounds__(512) void qproj_kernel(const float* __restrict__ query,
                                                    const float* __restrict__ Wq) {
    __shared__ float xs[HID];
    int b = blockIdx.x;
    xs[threadIdx.x] = query[b * HID + threadIdx.x];
    __syncthreads();
    const float4* xs4 = reinterpret_cast<const float4*>(xs);
    int w = threadIdx.x >> 5, lane = threadIdx.x & 31;
#pragma unroll
    for (int j = 0; j < 8; j++) {
        int o = blockIdx.y * 128 + w * 8 + j;
        const float4* wr = reinterpret_cast<const float4*>(Wq + (size_t)o * HID);
        float acc = 0.f;
#pragma unroll
        for (int s = 0; s < 4; s++) {
            float4 wv = wr[lane + 32 * s];
            float4 xv = xs4[lane + 32 * s];
            acc += wv.x * xv.x + wv.y * xv.y + wv.z * xv.z + wv.w * xv.w;
        }
#pragma unroll
        for (int off = 16; off > 0; off >>= 1)
            acc += __shfl_xor_sync(0xffffffffu, acc, off);
        if (lane == 0) g_q[b * HID + o] = acc * 0.125f;  // fold 1/sqrt(64)
    }
}

// ---------------------------------------------------------------------------
// Kernel 2: positional score GEMM over the visible window only.
// pe_s[n][m] = sum_d q[n][d] * key_pe[d][m].  64n x 64m tile, 4x4/thread.
// Tiles entirely inside the globally-masked region early-exit (never read).
// ---------------------------------------------------------------------------
__global__ void pe_kernel(const float* __restrict__ key_pe,
                          const float* __restrict__ span) {
    int m0 = blockIdx.x * 64;
    // earliest visible m over all heads = vis_start(max span)
    float smax = 0.f;
#pragma unroll
    for (int i = 0; i < NHEADS; i++) smax = fmaxf(smax, span[i]);
    if (m0 + 64 <= vis_start(smax * (float)MLEN)) return;

    __shared__ float qT[64][68];   // [d][n], padded
    __shared__ float pT[64][68];   // [d][m], padded
    int n0 = blockIdx.y * 64;
    int t = threadIdx.x;
#pragma unroll
    for (int j = 0; j < 16; j++) {
        int idx = t + 256 * j;
        int a = idx & 63;
        int c = idx >> 6;
        pT[c][a] = key_pe[c * MLEN + m0 + a];
        qT[a][c] = g_q[(n0 + c) * HD + a];
    }
    __syncthreads();
    int tx = t & 15, ty = t >> 4;
    float acc[4][4];
#pragma unroll
    for (int i = 0; i < 4; i++)
#pragma unroll
        for (int j = 0; j < 4; j++) acc[i][j] = 0.f;

#pragma unroll 4
    for (int d = 0; d < 64; d++) {
        float4 a4 = *reinterpret_cast<float4*>(&qT[d][ty * 4]);
        float4 b4 = *reinterpret_cast<float4*>(&pT[d][tx * 4]);
        float av[4] = {a4.x, a4.y, a4.z, a4.w};
        float bv[4] = {b4.x, b4.y, b4.z, b4.w};
#pragma unroll
        for (int i = 0; i < 4; i++)
#pragma unroll
            for (int j = 0; j < 4; j++) acc[i][j] = fmaf(av[i], bv[j], acc[i][j]);
    }
#pragma unroll
    for (int i = 0; i < 4; i++) {
        float4 r = make_float4(acc[i][0], acc[i][1], acc[i][2], acc[i][3]);
        *reinterpret_cast<float4*>(
            &g_pe[(size_t)(n0 + ty * 4 + i) * MLEN + m0 + tx * 4]) = r;
    }
}

// ---------------------------------------------------------------------------
// Kernel 3: split attention over the VISIBLE window only.
// grid (SPLIT, NTOT), 256 threads.  Window [mstart, M) is split into
// 16-aligned chunks; each CTA emits partial (lmax, z, zm, out[64]).
// ---------------------------------------------------------------------------
__global__ __launch_bounds__(256) void attn_split_kernel(const float* __restrict__ key,
                                                         const float* __restrict__ value,
                                                         const float* __restrict__ span) {
    __shared__ float s_sm[MAXCHUNK];   // scores, then weights e*mask
    __shared__ float red[512];
    __shared__ float wred[16];

    int split = blockIdx.x;
    int n = blockIdx.y;
    int t = threadIdx.x, w = t >> 5, lane = t & 31;
    int sl = lane & 15, half = lane >> 4;
    int ps = n * SPLIT + split;

    float spanM = span[n & (NHEADS - 1)] * (float)MLEN;
    int mstart = vis_start(spanM);
    int L = MLEN - mstart;
    int clen = (((L + SPLIT - 1) / SPLIT) + 15) & ~15;
    int a = mstart + split * clen;
    int bend = a + clen;
    if (bend > MLEN) bend = MLEN;

    if (a >= bend) {   // empty split (uniform branch)
        if (t < 64) g_pout[(size_t)ps * HD + t] = 0.f;
        if (t == 64) { g_pmax[ps] = -1e30f; g_pz[ps] = 0.f; g_pzm[ps] = 0.f; }
        return;
    }

    const float* krow = key + (size_t)n * MLEN * HD;
    const float* pen = &g_pe[(size_t)n * MLEN];
    float4 q4 = *reinterpret_cast<const float4*>(&g_q[n * HD + 4 * sl]);

    // ---- Phase 1: scores.  Warp does 2 rows/step (16-lane split).
    int iters = (bend - a + 15) >> 4;
    float lmax = -1e30f;
    for (int i = 0; i < iters; i++) {
        int m = a + i * 16 + w * 2 + half;
        float p = 0.f;
        if (m < bend) {
            float4 k4 = *(reinterpret_cast<const float4*>(krow + (size_t)m * HD) + sl);
            p = q4.x * k4.x + q4.y * k4.y + q4.z * k4.z + q4.w * k4.w;
        }
        p += __shfl_xor_sync(0xffffffffu, p, 8);
        p += __shfl_xor_sync(0xffffffffu, p, 4);
        p += __shfl_xor_sync(0xffffffffu, p, 2);
        p += __shfl_xor_sync(0xffffffffu, p, 1);
        float p1 = __shfl_sync(0xffffffffu, p, 16);
        if (lane == 0) {
            int mb = a + i * 16 + w * 2;
            float s0 = -1e30f, s1 = -1e30f;
            if (mb < bend)     s0 = pen[mb] + p;
            if (mb + 1 < bend) s1 = pen[mb + 1] + p1;
            *reinterpret_cast<float2*>(&s_sm[i * 16 + w * 2]) = make_float2(s0, s1);
            lmax = fmaxf(lmax, fmaxf(s0, s1));
        }
    }
    if (lane == 0) wred[w] = lmax;
    __syncthreads();
    float bmax = wred[0];
#pragma unroll
    for (int j = 1; j < 8; j++) bmax = fmaxf(bmax, wred[j]);

    // ---- Phase 2: exp, mask, partial sums (local-max scale).
    int padded = iters * 16;
    float z = 0.f, zm = 0.f;
    for (int ml = t; ml < padded; ml += 256) {
        int m = a + ml;
        float e = __expf(s_sm[ml] - bmax);   // padded rows: exp(-inf)=0
        float mk = ((float)(m + 1 - MLEN) + spanM) * (1.0f / 32.0f) + 1.0f;
        mk = fminf(fmaxf(mk, 0.f), 1.f);
        float em = e * mk;
        z += e;
        zm += em;
        s_sm[ml] = em;
    }
#pragma unroll
    for (int off = 16; off > 0; off >>= 1) {
        z += __shfl_xor_sync(0xffffffffu, z, off);
        zm += __shfl_xor_sync(0xffffffffu, zm, off);
    }
    if (lane == 0) { red[w] = z; red[8 + w] = zm; }
    __syncthreads();
    float zt = 0.f, zmt = 0.f;
#pragma unroll
    for (int j = 0; j < 8; j++) { zt += red[j]; zmt += red[8 + j]; }
    __syncthreads();   // red reused below; s_sm weights final

    // ---- Phase 3: partial out.  Warp owns all 64 dims (float2/lane).
    float2 acc = make_float2(0.f, 0.f);
    const float2* vb = reinterpret_cast<const float2*>(value + (size_t)n * MLEN * HD +
                                                       (size_t)a * HD) + lane;
    int mcount = bend - a;
    for (int ml = w; ml < mcount; ml += 8) {
        float wv = s_sm[ml];
        float2 v = vb[(size_t)ml * 32];
        acc.x = fmaf(wv, v.x, acc.x);
        acc.y = fmaf(wv, v.y, acc.y);
    }
    *reinterpret_cast<float2*>(&red[w * 64 + 2 * lane]) = acc;
    __syncthreads();
    if (t < 64) {
        float s = 0.f;
#pragma unroll
        for (int j = 0; j < 8; j++) s += red[j * 64 + t];
        g_pout[(size_t)ps * HD + t] = s;
    }
    if (t == 64) { g_pmax[ps] = bmax; g_pz[ps] = zt; g_pzm[ps] = zmt; }
}

// ---------------------------------------------------------------------------
// Kernel 4: combine splits + output projection, fused.
// grid (BATCH, 4), 512 threads.  Stage 1: ctx[512] in smem.  Stage 2: GEMV.
// ---------------------------------------------------------------------------
__global__ __launch_bounds__(512) void oproj_kernel(const float* __restrict__ Wo,
                                                    float* __restrict__ out) {
    __shared__ float xs[HID];
    int b = blockIdx.x;
    {   // stage 1: thread t owns (h = t>>6, d = t&63)
        int h = threadIdx.x >> 6, d = threadIdx.x & 63;
        int n = b * NHEADS + h;
        float lm[SPLIT];
        float gmax = -1e30f;
#pragma unroll
        for (int i = 0; i < SPLIT; i++) {
            lm[i] = g_pmax[n * SPLIT + i];
            gmax = fmaxf(gmax, lm[i]);
        }
        float Z = 0.f, Zm = 0.f, o = 0.f;
#pragma unroll
        for (int i = 0; i < SPLIT; i++) {
            float c = __expf(lm[i] - gmax);
            Z = fmaf(c, g_pz[n * SPLIT + i], Z);
            Zm = fmaf(c, g_pzm[n * SPLIT + i], Zm);
            o = fmaf(c, g_pout[(size_t)(n * SPLIT + i) * HD + d], o);
        }
        xs[threadIdx.x] = o / (Zm + 1e-8f * Z);
    }
    __syncthreads();
    const float4* xs4 = reinterpret_cast<const float4*>(xs);
    int w = threadIdx.x >> 5, lane = threadIdx.x & 31;
#pragma unroll
    for (int j = 0; j < 8; j++) {
        int o = blockIdx.y * 128 + w * 8 + j;
        const float4* wr = reinterpret_cast<const float4*>(Wo + (size_t)o * HID);
        float acc = 0.f;
#pragma unroll
        for (int s = 0; s < 4; s++) {
            float4 wv = wr[lane + 32 * s];
            float4 xv = xs4[lane + 32 * s];
            acc += wv.x * xv.x + wv.y * xv.y + wv.z * xv.z + wv.w * xv.w;
        }
#pragma unroll
        for (int off = 16; off > 0; off >>= 1)
            acc += __shfl_xor_sync(0xffffffffu, acc, off);
        if (lane == 0) out[b * HID + o] = acc;
    }
}

// ---------------------------------------------------------------------------
extern "C" void kernel_launch(void* const* d_in, const int* in_sizes, int n_in,
                              void* d_out, int out_size) {
    const float* query  = (const float*)d_in[0];
    const float* key    = (const float*)d_in[1];
    const float* value  = (const float*)d_in[2];
    const float* Wq     = (const float*)d_in[3];
    const float* Wo     = (const float*)d_in[4];
    const float* key_pe = (const float*)d_in[5];
    const float* span   = (const float*)d_in[6];
    float* out = (float*)d_out;
    (void)in_sizes; (void)n_in; (void)out_size;

    qproj_kernel<<<dim3(BATCH, 4), 512>>>(query, Wq);
    pe_kernel<<<dim3(MLEN / 64, NTOT / 64), 256>>>(key_pe, span);
    attn_split_kernel<<<dim3(SPLIT, NTOT), 256>>>(key, value, span);
    oproj_kernel<<<dim3(BATCH, 4), 512>>>(Wo, out);
}

// round 4
// speedup vs baseline: 2.5535x; 1.0719x over previous
#include <cuda_runtime.h>
#include <math.h>

#define BATCH 32
#define NHEADS 8
#define HD 64
#define HID 512
#define MLEN 8192
#define NTOT 256          // BATCH*NHEADS
#define SPLIT 16
#define CHUNKMAX 512      // ceil over splits, 16-aligned, <= 512
#define TILE_M 128

// scratch (static device globals — no runtime allocation)
__device__ float g_q[NTOT * HD];
__device__ float g_pe[NTOT * MLEN];
__device__ float g_ctx[BATCH * HID];
__device__ float g_pmax[NTOT * SPLIT];
__device__ float g_pz[NTOT * SPLIT];
__device__ float g_pzm[NTOT * SPLIT];
__device__ float g_pout[NTOT * SPLIT * HD];

// mask == 0 for m <= M-33-spanM; -2 margin for float rounding safety
__device__ __forceinline__ int vis_start(float spanM) {
    int ms = (int)floorf((float)(MLEN - 33) - spanM) - 2;
    return ms < 0 ? 0 : ms;
}

// ---------------------------------------------------------------------------
// Kernel 1: q projection.  grid (BATCH, 4), 512 threads.
// ---------------------------------------------------------------------------
__global__ __launch_bounds__(512) void qproj_kernel(const float* __restrict__ query,
                                                    const float* __restrict__ Wq) {
    __shared__ float xs[HID];
    int b = blockIdx.x;
    xs[threadIdx.x] = query[b * HID + threadIdx.x];
    __syncthreads();
    const float4* xs4 = reinterpret_cast<const float4*>(xs);
    int w = threadIdx.x >> 5, lane = threadIdx.x & 31;
#pragma unroll
    for (int j = 0; j < 8; j++) {
        int o = blockIdx.y * 128 + w * 8 + j;
        const float4* wr = reinterpret_cast<const float4*>(Wq + (size_t)o * HID);
        float acc = 0.f;
#pragma unroll
        for (int s = 0; s < 4; s++) {
            float4 wv = wr[lane + 32 * s];
            float4 xv = xs4[lane + 32 * s];
            acc += wv.x * xv.x + wv.y * xv.y + wv.z * xv.z + wv.w * xv.w;
        }
#pragma unroll
        for (int off = 16; off > 0; off >>= 1)
            acc += __shfl_xor_sync(0xffffffffu, acc, off);
        if (lane == 0) g_q[b * HID + o] = acc * 0.125f;  // fold 1/sqrt(64)
    }
}

// ---------------------------------------------------------------------------
// Kernel 2: positional score GEMM over the visible window only.
// ---------------------------------------------------------------------------
__global__ void pe_kernel(const float* __restrict__ key_pe,
                          const float* __restrict__ span) {
    int m0 = blockIdx.x * 64;
    float smax = 0.f;
#pragma unroll
    for (int i = 0; i < NHEADS; i++) smax = fmaxf(smax, span[i]);
    if (m0 + 64 <= vis_start(smax * (float)MLEN)) return;

    __shared__ float qT[64][68];
    __shared__ float pT[64][68];
    int n0 = blockIdx.y * 64;
    int t = threadIdx.x;
#pragma unroll
    for (int j = 0; j < 16; j++) {
        int idx = t + 256 * j;
        int a = idx & 63;
        int c = idx >> 6;
        pT[c][a] = key_pe[c * MLEN + m0 + a];
        qT[a][c] = g_q[(n0 + c) * HD + a];
    }
    __syncthreads();
    int tx = t & 15, ty = t >> 4;
    float acc[4][4];
#pragma unroll
    for (int i = 0; i < 4; i++)
#pragma unroll
        for (int j = 0; j < 4; j++) acc[i][j] = 0.f;

#pragma unroll 4
    for (int d = 0; d < 64; d++) {
        float4 a4 = *reinterpret_cast<float4*>(&qT[d][ty * 4]);
        float4 b4 = *reinterpret_cast<float4*>(&pT[d][tx * 4]);
        float av[4] = {a4.x, a4.y, a4.z, a4.w};
        float bv[4] = {b4.x, b4.y, b4.z, b4.w};
#pragma unroll
        for (int i = 0; i < 4; i++)
#pragma unroll
            for (int j = 0; j < 4; j++) acc[i][j] = fmaf(av[i], bv[j], acc[i][j]);
    }
#pragma unroll
    for (int i = 0; i < 4; i++) {
        float4 r = make_float4(acc[i][0], acc[i][1], acc[i][2], acc[i][3]);
        *reinterpret_cast<float4*>(
            &g_pe[(size_t)(n0 + ty * 4 + i) * MLEN + m0 + tx * 4]) = r;
    }
}

// ---------------------------------------------------------------------------
// Kernel 3: split attention, visible window only.  grid (SPLIT, NTOT), 128 thr.
// Phase 1: K staged via XOR-swizzled smem tiles, thread-per-m dot (no shfl).
// Phase 2: exp + mask + partial sums.  Phase 3: float4 value accumulation.
// ---------------------------------------------------------------------------
__global__ __launch_bounds__(128) void attn_split_kernel(const float* __restrict__ key,
                                                         const float* __restrict__ value,
                                                         const float* __restrict__ span) {
    __shared__ float4 Ks4[TILE_M * 16];   // 32 KB, XOR-swizzled
    __shared__ float4 qs4[16];
    __shared__ float s_sm[CHUNKMAX];      // scores -> weights
    __shared__ float red[4 * 64];
    __shared__ float wred[4], zr[4], zmr[4];

    int split = blockIdx.x;
    int n = blockIdx.y;
    int t = threadIdx.x, w = t >> 5, lane = t & 31;
    int ps = n * SPLIT + split;

    float spanM = span[n & (NHEADS - 1)] * (float)MLEN;
    int mstart = vis_start(spanM);
    int L = MLEN - mstart;
    int clen = (((L + SPLIT - 1) / SPLIT) + 15) & ~15;
    int a = mstart + split * clen;
    int bend = a + clen;
    if (bend > MLEN) bend = MLEN;

    if (a >= bend) {   // empty split (uniform branch)
        if (t < 64) g_pout[(size_t)ps * HD + t] = 0.f;
        if (t == 64) { g_pmax[ps] = -1e30f; g_pz[ps] = 0.f; g_pzm[ps] = 0.f; }
        return;
    }
    int cnt = bend - a;
    int ntiles = (cnt + TILE_M - 1) >> 7;

    if (t < 16) qs4[t] = reinterpret_cast<const float4*>(g_q + n * HD)[t];
    const float4* ksrc = reinterpret_cast<const float4*>(key + (size_t)n * MLEN * HD);
    const float* pen = g_pe + (size_t)n * MLEN;

    // ---- Phase 1: tiled scores, no shuffles.
    float lmax = -1e30f;
    for (int tile = 0; tile < ntiles; tile++) {
        int gm = a + (tile << 7);
        int R = bend - gm; if (R > TILE_M) R = TILE_M;
        __syncthreads();   // protect Ks reuse (and qs4 on first pass)
#pragma unroll
        for (int j = 0; j < 16; j++) {
            int idx = t + 128 * j;
            int row = idx >> 4, c = idx & 15;
            if (row < R)
                Ks4[(row << 4) + (c ^ (row & 15))] = ksrc[(size_t)(gm + row) * 16 + c];
        }
        __syncthreads();
        int ml = (tile << 7) + t;
        if (t < R) {
            float s0 = 0.f, s1 = 0.f;
#pragma unroll 4
            for (int c = 0; c < 16; c++) {
                float4 kv = Ks4[(t << 4) + (c ^ (t & 15))];
                float4 qv = qs4[c];
                s0 = fmaf(kv.x, qv.x, fmaf(kv.y, qv.y, s0));
                s1 = fmaf(kv.z, qv.z, fmaf(kv.w, qv.w, s1));
            }
            float sc = s0 + s1 + pen[gm + t];
            s_sm[ml] = sc;
            lmax = fmaxf(lmax, sc);
        } else {
            s_sm[ml] = -1e30f;
        }
    }
#pragma unroll
    for (int off = 16; off > 0; off >>= 1)
        lmax = fmaxf(lmax, __shfl_xor_sync(0xffffffffu, lmax, off));
    if (lane == 0) wred[w] = lmax;
    __syncthreads();
    float bmax = fmaxf(fmaxf(wred[0], wred[1]), fmaxf(wred[2], wred[3]));

    // ---- Phase 2: exp, mask, partial sums (local-max scale).
    int padded = ntiles << 7;
    float z = 0.f, zm = 0.f;
#pragma unroll 4
    for (int ml = t; ml < padded; ml += 128) {
        int m = a + ml;
        float e = __expf(s_sm[ml] - bmax);   // padded entries -> 0
        float mk = ((float)(m + 1 - MLEN) + spanM) * (1.0f / 32.0f) + 1.0f;
        mk = fminf(fmaxf(mk, 0.f), 1.f);
        float em = e * mk;
        z += e;
        zm += em;
        s_sm[ml] = em;
    }
#pragma unroll
    for (int off = 16; off > 0; off >>= 1) {
        z += __shfl_xor_sync(0xffffffffu, z, off);
        zm += __shfl_xor_sync(0xffffffffu, zm, off);
    }
    if (lane == 0) { zr[w] = z; zmr[w] = zm; }
    __syncthreads();
    float zt = zr[0] + zr[1] + zr[2] + zr[3];
    float zmt = zmr[0] + zmr[1] + zmr[2] + zmr[3];

    // ---- Phase 3: partial out.  16-lane split, float4/lane, 512B/warp/instr.
    int sl = lane & 15, half = lane >> 4;
    const float4* vb = reinterpret_cast<const float4*>(value + (size_t)n * MLEN * HD +
                                                       (size_t)a * HD);
    float4 acc = make_float4(0.f, 0.f, 0.f, 0.f);
#pragma unroll 4
    for (int i = w * 2 + half; i < cnt; i += 8) {
        float wv = s_sm[i];
        float4 v = vb[(size_t)i * 16 + sl];
        acc.x = fmaf(wv, v.x, acc.x);
        acc.y = fmaf(wv, v.y, acc.y);
        acc.z = fmaf(wv, v.z, acc.z);
        acc.w = fmaf(wv, v.w, acc.w);
    }
    acc.x += __shfl_xor_sync(0xffffffffu, acc.x, 16);
    acc.y += __shfl_xor_sync(0xffffffffu, acc.y, 16);
    acc.z += __shfl_xor_sync(0xffffffffu, acc.z, 16);
    acc.w += __shfl_xor_sync(0xffffffffu, acc.w, 16);
    __syncthreads();   // s_sm no longer needed; red reuse safe
    if (lane < 16) *reinterpret_cast<float4*>(&red[w * 64 + 4 * sl]) = acc;
    __syncthreads();
    if (t < 64) {
        float s = red[t] + red[64 + t] + red[128 + t] + red[192 + t];
        g_pout[(size_t)ps * HD + t] = s;
    }
    if (t == 64) { g_pmax[ps] = bmax; g_pz[ps] = zt; g_pzm[ps] = zmt; }
}

// ---------------------------------------------------------------------------
// Kernel 4: combine splits.  grid NTOT, 64 threads.
// ---------------------------------------------------------------------------
__global__ __launch_bounds__(64) void combine_kernel() {
    __shared__ float cm[SPLIT], cz[SPLIT], czm[SPLIT];
    int n = blockIdx.x, d = threadIdx.x;
    if (d < SPLIT) {
        cm[d] = g_pmax[n * SPLIT + d];
        cz[d] = g_pz[n * SPLIT + d];
        czm[d] = g_pzm[n * SPLIT + d];
    }
    __syncthreads();
    float gmax = -1e30f;
#pragma unroll
    for (int i = 0; i < SPLIT; i++) gmax = fmaxf(gmax, cm[i]);
    float Z = 0.f, Zm = 0.f, o = 0.f;
#pragma unroll
    for (int i = 0; i < SPLIT; i++) {
        float c = __expf(cm[i] - gmax);
        Z = fmaf(c, cz[i], Z);
        Zm = fmaf(c, czm[i], Zm);
        o = fmaf(c, g_pout[(size_t)(n * SPLIT + i) * HD + d], o);
    }
    g_ctx[n * HD + d] = o / (Zm + 1e-8f * Z);
}

// ---------------------------------------------------------------------------
// Kernel 5: output projection GEMV.  grid (BATCH, 4), 512 threads.
// ---------------------------------------------------------------------------
__global__ __launch_bounds__(512) void oproj_kernel(const float* __restrict__ Wo,
                                                    float* __restrict__ out) {
    __shared__ float xs[HID];
    int b = blockIdx.x;
    xs[threadIdx.x] = g_ctx[b * HID + threadIdx.x];
    __syncthreads();
    const float4* xs4 = reinterpret_cast<const float4*>(xs);
    int w = threadIdx.x >> 5, lane = threadIdx.x & 31;
#pragma unroll
    for (int j = 0; j < 8; j++) {
        int o = blockIdx.y * 128 + w * 8 + j;
        const float4* wr = reinterpret_cast<const float4*>(Wo + (size_t)o * HID);
        float acc = 0.f;
#pragma unroll
        for (int s = 0; s < 4; s++) {
            float4 wv = wr[lane + 32 * s];
            float4 xv = xs4[lane + 32 * s];
            acc += wv.x * xv.x + wv.y * xv.y + wv.z * xv.z + wv.w * xv.w;
        }
#pragma unroll
        for (int off = 16; off > 0; off >>= 1)
            acc += __shfl_xor_sync(0xffffffffu, acc, off);
        if (lane == 0) out[b * HID + o] = acc;
    }
}

// ---------------------------------------------------------------------------
extern "C" void kernel_launch(void* const* d_in, const int* in_sizes, int n_in,
                              void* d_out, int out_size) {
    const float* query  = (const float*)d_in[0];
    const float* key    = (const float*)d_in[1];
    const float* value  = (const float*)d_in[2];
    const float* Wq     = (const float*)d_in[3];
    const float* Wo     = (const float*)d_in[4];
    const float* key_pe = (const float*)d_in[5];
    const float* span   = (const float*)d_in[6];
    float* out = (float*)d_out;
    (void)in_sizes; (void)n_in; (void)out_size;

    qproj_kernel<<<dim3(BATCH, 4), 512>>>(query, Wq);
    pe_kernel<<<dim3(MLEN / 64, NTOT / 64), 256>>>(key_pe, span);
    attn_split_kernel<<<dim3(SPLIT, NTOT), 128>>>(key, value, span);
    combine_kernel<<<NTOT, 64>>>();
    oproj_kernel<<<dim3(BATCH, 4), 512>>>(Wo, out);
}

// round 6
// speedup vs baseline: 3.0580x; 1.1976x over previous
#include <cuda_runtime.h>
#include <cstdint>
#include <math.h>

#define BATCH 32
#define NHEADS 8
#define HD 64
#define HID 512
#define MLEN 8192
#define NTOT 256          // BATCH*NHEADS
#define SPLIT 16
#define CHUNKMAX 512      // max chunk (16-aligned)
#define HT 64             // half-tile rows (double-buffered)

// scratch (static device globals — no runtime allocation)
__device__ float g_q[NTOT * HD];
__device__ float g_pe[NTOT * MLEN];
__device__ float g_pmax[NTOT * SPLIT];
__device__ float g_pz[NTOT * SPLIT];
__device__ float g_pzm[NTOT * SPLIT];
__device__ float g_pout[NTOT * SPLIT * HD];

// mask == 0 for m <= M-33-spanM; -2 margin for float rounding safety
__device__ __forceinline__ int vis_start(float spanM) {
    int ms = (int)floorf((float)(MLEN - 33) - spanM) - 2;
    return ms < 0 ? 0 : ms;
}

__device__ __forceinline__ void cp_async16(unsigned int saddr, const void* gptr) {
    asm volatile("cp.async.cg.shared.global [%0], [%1], 16;\n"
                 :: "r"(saddr), "l"(gptr) : "memory");
}
__device__ __forceinline__ void cp_commit() {
    asm volatile("cp.async.commit_group;\n" ::: "memory");
}

// ---------------------------------------------------------------------------
// Kernel 1: q projection.  grid (BATCH, 4), 512 threads.
// ---------------------------------------------------------------------------
__global__ __launch_bounds__(512) void qproj_kernel(const float* __restrict__ query,
                                                    const float* __restrict__ Wq) {
    __shared__ float xs[HID];
    int b = blockIdx.x;
    xs[threadIdx.x] = query[b * HID + threadIdx.x];
    __syncthreads();
    const float4* xs4 = reinterpret_cast<const float4*>(xs);
    int w = threadIdx.x >> 5, lane = threadIdx.x & 31;
#pragma unroll
    for (int j = 0; j < 8; j++) {
        int o = blockIdx.y * 128 + w * 8 + j;
        const float4* wr = reinterpret_cast<const float4*>(Wq + (size_t)o * HID);
        float acc = 0.f;
#pragma unroll
        for (int s = 0; s < 4; s++) {
            float4 wv = wr[lane + 32 * s];
            float4 xv = xs4[lane + 32 * s];
            acc += wv.x * xv.x + wv.y * xv.y + wv.z * xv.z + wv.w * xv.w;
        }
#pragma unroll
        for (int off = 16; off > 0; off >>= 1)
            acc += __shfl_xor_sync(0xffffffffu, acc, off);
        if (lane == 0) g_q[b * HID + o] = acc * 0.125f;  // fold 1/sqrt(64)
    }
}

// ---------------------------------------------------------------------------
// Kernel 2: positional score GEMM over the visible window only.
// ---------------------------------------------------------------------------
__global__ void pe_kernel(const float* __restrict__ key_pe,
                          const float* __restrict__ span) {
    int m0 = blockIdx.x * 64;
    float smax = 0.f;
#pragma unroll
    for (int i = 0; i < NHEADS; i++) smax = fmaxf(smax, span[i]);
    if (m0 + 64 <= vis_start(smax * (float)MLEN)) return;

    __shared__ float qT[64][68];
    __shared__ float pT[64][68];
    int n0 = blockIdx.y * 64;
    int t = threadIdx.x;
#pragma unroll
    for (int j = 0; j < 16; j++) {
        int idx = t + 256 * j;
        int a = idx & 63;
        int c = idx >> 6;
        pT[c][a] = key_pe[c * MLEN + m0 + a];
        qT[a][c] = g_q[(n0 + c) * HD + a];
    }
    __syncthreads();
    int tx = t & 15, ty = t >> 4;
    float acc[4][4];
#pragma unroll
    for (int i = 0; i < 4; i++)
#pragma unroll
        for (int j = 0; j < 4; j++) acc[i][j] = 0.f;

#pragma unroll 4
    for (int d = 0; d < 64; d++) {
        float4 a4 = *reinterpret_cast<float4*>(&qT[d][ty * 4]);
        float4 b4 = *reinterpret_cast<float4*>(&pT[d][tx * 4]);
        float av[4] = {a4.x, a4.y, a4.z, a4.w};
        float bv[4] = {b4.x, b4.y, b4.z, b4.w};
#pragma unroll
        for (int i = 0; i < 4; i++)
#pragma unroll
            for (int j = 0; j < 4; j++) acc[i][j] = fmaf(av[i], bv[j], acc[i][j]);
    }
#pragma unroll
    for (int i = 0; i < 4; i++) {
        float4 r = make_float4(acc[i][0], acc[i][1], acc[i][2], acc[i][3]);
        *reinterpret_cast<float4*>(
            &g_pe[(size_t)(n0 + ty * 4 + i) * MLEN + m0 + tx * 4]) = r;
    }
}

// ---------------------------------------------------------------------------
// Kernel 3: split attention, visible window only.  grid (SPLIT, NTOT), 128 thr.
// Phase 1: cp.async double-buffered 64-row K half-tiles; 64 rows x 2 k-halves
//          per 128 threads (partials in sA/sB, no shuffles, conflict-free LDS).
// Phase 2: combine partials + pe, block max, exp + mask + sums.
// Phase 3: float4 value streaming.
// ---------------------------------------------------------------------------
__global__ __launch_bounds__(128) void attn_split_kernel(const float* __restrict__ key,
                                                         const float* __restrict__ value,
                                                         const float* __restrict__ span) {
    __shared__ float4 Ks4[2][HT * 16];    // 32 KB, XOR-swizzled, double buffer
    __shared__ float4 qs4[16];
    __shared__ float sA[CHUNKMAX];        // k-half-0 partials -> scores -> weights
    __shared__ float sB[CHUNKMAX];        // k-half-1 partials -> out reduction
    __shared__ float wred[4], zr[4], zmr[4];

    int split = blockIdx.x;
    int n = blockIdx.y;
    int t = threadIdx.x, w = t >> 5, lane = t & 31;
    int ps = n * SPLIT + split;

    float spanM = span[n & (NHEADS - 1)] * (float)MLEN;
    int mstart = vis_start(spanM);
    int L = MLEN - mstart;
    int clen = (((L + SPLIT - 1) / SPLIT) + 15) & ~15;
    int a = mstart + split * clen;
    int bend = a + clen;
    if (bend > MLEN) bend = MLEN;

    if (a >= bend) {   // empty split (uniform branch)
        if (t < 64) g_pout[(size_t)ps * HD + t] = 0.f;
        if (t == 64) { g_pmax[ps] = -1e30f; g_pz[ps] = 0.f; g_pzm[ps] = 0.f; }
        return;
    }
    int cnt = bend - a;
    int nht = (cnt + HT - 1) >> 6;

    if (t < 16) qs4[t] = reinterpret_cast<const float4*>(g_q + n * HD)[t];
    const float4* ksrc = reinterpret_cast<const float4*>(key + (size_t)n * MLEN * HD);
    const float* pen = g_pe + (size_t)n * MLEN;
    unsigned int ks_smem = (unsigned int)__cvta_generic_to_shared(&Ks4[0][0]);

    // issue one half-tile's cp.async group (uniform across block)
    auto issue_ht = [&](int h) {
        int gm = a + (h << 6);
        int R = bend - gm; if (R > HT) R = HT;
        unsigned int base = ks_smem + (unsigned int)(h & 1) * (HT * 16 * 16);
#pragma unroll
        for (int j = 0; j < 8; j++) {
            int idx = t + 128 * j;
            int row = idx >> 4, c = idx & 15;
            if (row < R)
                cp_async16(base + (unsigned int)(((row << 4) + (c ^ (row & 15))) * 16),
                           ksrc + (size_t)(gm + row) * 16 + c);
        }
        cp_commit();
    };

    issue_ht(0);
    if (nht > 1) issue_ht(1);

    // ---- Phase 1: pipelined partial dots.
    int r = t & 63, kh = t >> 6;
    for (int h = 0; h < nht; h++) {
        if (h + 1 < nht) asm volatile("cp.async.wait_group 1;\n" ::: "memory");
        else             asm volatile("cp.async.wait_group 0;\n" ::: "memory");
        __syncthreads();
        int gm = a + (h << 6);
        int R = bend - gm; if (R > HT) R = HT;
        float part = 0.f;
        if (r < R) {
            const float4* buf = Ks4[h & 1];
#pragma unroll
            for (int j = 0; j < 8; j++) {
                int c = kh * 8 + j;
                float4 kv = buf[(r << 4) + (c ^ (r & 15))];
                float4 qv = qs4[c];
                part = fmaf(kv.x, qv.x, fmaf(kv.y, qv.y,
                        fmaf(kv.z, qv.z, fmaf(kv.w, qv.w, part))));
            }
        }
        int ml = (h << 6) + r;
        if (kh == 0) sA[ml] = part; else sB[ml] = part;
        __syncthreads();            // buffer free before re-fill
        if (h + 2 < nht) issue_ht(h + 2);
    }

    // ---- Phase 2a: combine partials + pe, block max.
    int padded = nht << 6;
    float lmax = -1e30f;
#pragma unroll 4
    for (int ml = t; ml < padded; ml += 128) {
        float sc = (ml < cnt) ? sA[ml] + sB[ml] + pen[a + ml] : -1e30f;
        sA[ml] = sc;
        lmax = fmaxf(lmax, sc);
    }
#pragma unroll
    for (int off = 16; off > 0; off >>= 1)
        lmax = fmaxf(lmax, __shfl_xor_sync(0xffffffffu, lmax, off));
    if (lane == 0) wred[w] = lmax;
    __syncthreads();
    float bmax = fmaxf(fmaxf(wred[0], wred[1]), fmaxf(wred[2], wred[3]));

    // ---- Phase 2b: exp, mask, partial sums (local-max scale).
    float z = 0.f, zm = 0.f;
#pragma unroll 4
    for (int ml = t; ml < padded; ml += 128) {
        int m = a + ml;
        float e = __expf(sA[ml] - bmax);   // padded entries -> 0
        float mk = ((float)(m + 1 - MLEN) + spanM) * (1.0f / 32.0f) + 1.0f;
        mk = fminf(fmaxf(mk, 0.f), 1.f);
        float em = e * mk;
        z += e;
        zm += em;
        sA[ml] = em;
    }
#pragma unroll
    for (int off = 16; off > 0; off >>= 1) {
        z += __shfl_xor_sync(0xffffffffu, z, off);
        zm += __shfl_xor_sync(0xffffffffu, zm, off);
    }
    if (lane == 0) { zr[w] = z; zmr[w] = zm; }
    __syncthreads();
    float zt = zr[0] + zr[1] + zr[2] + zr[3];
    float zmt = zmr[0] + zmr[1] + zmr[2] + zmr[3];

    // ---- Phase 3: partial out.  16-lane split, float4/lane, 512B/warp/instr.
    int sl = lane & 15, half = lane >> 4;
    const float4* vb = reinterpret_cast<const float4*>(value + (size_t)n * MLEN * HD +
                                                       (size_t)a * HD);
    float4 acc = make_float4(0.f, 0.f, 0.f, 0.f);
#pragma unroll 4
    for (int i = w * 2 + half; i < cnt; i += 8) {
        float wv = sA[i];
        float4 v = vb[(size_t)i * 16 + sl];
        acc.x = fmaf(wv, v.x, acc.x);
        acc.y = fmaf(wv, v.y, acc.y);
        acc.z = fmaf(wv, v.z, acc.z);
        acc.w = fmaf(wv, v.w, acc.w);
    }
    acc.x += __shfl_xor_sync(0xffffffffu, acc.x, 16);
    acc.y += __shfl_xor_sync(0xffffffffu, acc.y, 16);
    acc.z += __shfl_xor_sync(0xffffffffu, acc.z, 16);
    acc.w += __shfl_xor_sync(0xffffffffu, acc.w, 16);
    __syncthreads();   // sB partials fully consumed in 2a; safe to reuse
    if (lane < 16) *reinterpret_cast<float4*>(&sB[w * 64 + 4 * sl]) = acc;
    __syncthreads();
    if (t < 64) {
        float s = sB[t] + sB[64 + t] + sB[128 + t] + sB[192 + t];
        g_pout[(size_t)ps * HD + t] = s;
    }
    if (t == 64) { g_pmax[ps] = bmax; g_pz[ps] = zt; g_pzm[ps] = zmt; }
}

// ---------------------------------------------------------------------------
// Kernel 4: combine splits + output projection, fused.
// grid (BATCH, 4), 512 threads.  Stage 1: ctx[512] in smem.  Stage 2: GEMV.
// ---------------------------------------------------------------------------
__global__ __launch_bounds__(512) void oproj_kernel(const float* __restrict__ Wo,
                                                    float* __restrict__ out) {
    __shared__ float xs[HID];
    int b = blockIdx.x;
    {   // stage 1: thread t owns (h = t>>6, d = t&63)
        int h = threadIdx.x >> 6, d = threadIdx.x & 63;
        int n = b * NHEADS + h;
        float gmax = -1e30f;
#pragma unroll
        for (int i = 0; i < SPLIT; i++) gmax = fmaxf(gmax, g_pmax[n * SPLIT + i]);
        float Z = 0.f, Zm = 0.f, o = 0.f;
#pragma unroll
        for (int i = 0; i < SPLIT; i++) {
            float c = __expf(g_pmax[n * SPLIT + i] - gmax);
            Z = fmaf(c, g_pz[n * SPLIT + i], Z);
            Zm = fmaf(c, g_pzm[n * SPLIT + i], Zm);
            o = fmaf(c, g_pout[(size_t)(n * SPLIT + i) * HD + d], o);
        }
        xs[threadIdx.x] = o / (Zm + 1e-8f * Z);
    }
    __syncthreads();
    const float4* xs4 = reinterpret_cast<const float4*>(xs);
    int w = threadIdx.x >> 5, lane = threadIdx.x & 31;
#pragma unroll
    for (int j = 0; j < 8; j++) {
        int o = blockIdx.y * 128 + w * 8 + j;
        const float4* wr = reinterpret_cast<const float4*>(Wo + (size_t)o * HID);
        float acc = 0.f;
#pragma unroll
        for (int s = 0; s < 4; s++) {
            float4 wv = wr[lane + 32 * s];
            float4 xv = xs4[lane + 32 * s];
            acc += wv.x * xv.x + wv.y * xv.y + wv.z * xv.z + wv.w * xv.w;
        }
#pragma unroll
        for (int off = 16; off > 0; off >>= 1)
            acc += __shfl_xor_sync(0xffffffffu, acc, off);
        if (lane == 0) out[b * HID + o] = acc;
    }
}

// ---------------------------------------------------------------------------
extern "C" void kernel_launch(void* const* d_in, const int* in_sizes, int n_in,
                              void* d_out, int out_size) {
    const float* query  = (const float*)d_in[0];
    const float* key    = (const float*)d_in[1];
    const float* value  = (const float*)d_in[2];
    const float* Wq     = (const float*)d_in[3];
    const float* Wo     = (const float*)d_in[4];
    const float* key_pe = (const float*)d_in[5];
    const float* span   = (const float*)d_in[6];
    float* out = (float*)d_out;
    (void)in_sizes; (void)n_in; (void)out_size;

    qproj_kernel<<<dim3(BATCH, 4), 512>>>(query, Wq);
    pe_kernel<<<dim3(MLEN / 64, NTOT / 64), 256>>>(key_pe, span);
    attn_split_kernel<<<dim3(SPLIT, NTOT), 128>>>(key, value, span);
    oproj_kernel<<<dim3(BATCH, 4), 512>>>(Wo, out);
}

// round 7
// speedup vs baseline: 3.2129x; 1.0506x over previous
#include <cuda_runtime.h>
#include <cstdint>
#include <math.h>

#define BATCH 32
#define NHEADS 8
#define HD 64
#define HID 512
#define MLEN 8192
#define NTOT 256          // BATCH*NHEADS
#define SPLIT 16
#define CHUNKMAX 512      // max chunk (16-aligned)
#define HT 64             // half-tile rows (double-buffered)

// scratch (static device globals — no runtime allocation)
__device__ float g_q[NTOT * HD];
__device__ float g_pe[NTOT * MLEN];
__device__ float g_pmax[NTOT * SPLIT];
__device__ float g_pz[NTOT * SPLIT];
__device__ float g_pzm[NTOT * SPLIT];
__device__ float g_pout[NTOT * SPLIT * HD];

// mask == 0 for m <= M-33-spanM; -2 margin for float rounding safety
__device__ __forceinline__ int vis_start(float spanM) {
    int ms = (int)floorf((float)(MLEN - 33) - spanM) - 2;
    return ms < 0 ? 0 : ms;
}

__device__ __forceinline__ void cp_async16(unsigned int saddr, const void* gptr) {
    asm volatile("cp.async.cg.shared.global [%0], [%1], 16;\n"
                 :: "r"(saddr), "l"(gptr) : "memory");
}
__device__ __forceinline__ void cp_commit() {
    asm volatile("cp.async.commit_group;\n" ::: "memory");
}

// ---------------------------------------------------------------------------
// Kernel 1: q projection.  grid (BATCH, 16), 512 threads; warp -> 2 outputs.
// ---------------------------------------------------------------------------
__global__ __launch_bounds__(512) void qproj_kernel(const float* __restrict__ query,
                                                    const float* __restrict__ Wq) {
    __shared__ float xs[HID];
    int b = blockIdx.x;
    xs[threadIdx.x] = query[b * HID + threadIdx.x];
    __syncthreads();
    const float4* xs4 = reinterpret_cast<const float4*>(xs);
    int w = threadIdx.x >> 5, lane = threadIdx.x & 31;
#pragma unroll
    for (int j = 0; j < 2; j++) {
        int o = blockIdx.y * 32 + w * 2 + j;
        const float4* wr = reinterpret_cast<const float4*>(Wq + (size_t)o * HID);
        float acc = 0.f;
#pragma unroll
        for (int s = 0; s < 4; s++) {
            float4 wv = wr[lane + 32 * s];
            float4 xv = xs4[lane + 32 * s];
            acc += wv.x * xv.x + wv.y * xv.y + wv.z * xv.z + wv.w * xv.w;
        }
#pragma unroll
        for (int off = 16; off > 0; off >>= 1)
            acc += __shfl_xor_sync(0xffffffffu, acc, off);
        if (lane == 0) g_q[b * HID + o] = acc * 0.125f;  // fold 1/sqrt(64)
    }
}

// ---------------------------------------------------------------------------
// Kernel 2: positional score GEMM over the visible window only.
// ---------------------------------------------------------------------------
__global__ void pe_kernel(const float* __restrict__ key_pe,
                          const float* __restrict__ span) {
    int m0 = blockIdx.x * 64;
    float smax = 0.f;
#pragma unroll
    for (int i = 0; i < NHEADS; i++) smax = fmaxf(smax, span[i]);
    if (m0 + 64 <= vis_start(smax * (float)MLEN)) return;

    __shared__ float qT[64][68];
    __shared__ float pT[64][68];
    int n0 = blockIdx.y * 64;
    int t = threadIdx.x;
#pragma unroll
    for (int j = 0; j < 16; j++) {
        int idx = t + 256 * j;
        int a = idx & 63;
        int c = idx >> 6;
        pT[c][a] = key_pe[c * MLEN + m0 + a];
        qT[a][c] = g_q[(n0 + c) * HD + a];
    }
    __syncthreads();
    int tx = t & 15, ty = t >> 4;
    float acc[4][4];
#pragma unroll
    for (int i = 0; i < 4; i++)
#pragma unroll
        for (int j = 0; j < 4; j++) acc[i][j] = 0.f;

#pragma unroll 4
    for (int d = 0; d < 64; d++) {
        float4 a4 = *reinterpret_cast<float4*>(&qT[d][ty * 4]);
        float4 b4 = *reinterpret_cast<float4*>(&pT[d][tx * 4]);
        float av[4] = {a4.x, a4.y, a4.z, a4.w};
        float bv[4] = {b4.x, b4.y, b4.z, b4.w};
#pragma unroll
        for (int i = 0; i < 4; i++)
#pragma unroll
            for (int j = 0; j < 4; j++) acc[i][j] = fmaf(av[i], bv[j], acc[i][j]);
    }
#pragma unroll
    for (int i = 0; i < 4; i++) {
        float4 r = make_float4(acc[i][0], acc[i][1], acc[i][2], acc[i][3]);
        *reinterpret_cast<float4*>(
            &g_pe[(size_t)(n0 + ty * 4 + i) * MLEN + m0 + tx * 4]) = r;
    }
}

// ---------------------------------------------------------------------------
// Kernel 3: split attention, visible window only.  grid (SPLIT, NTOT), 256 thr.
// Phase 1: cp.async double-buffered 64-row K half-tiles; 64 rows x 4 k-quarters
//          per 256 threads (partials in sP[4], no shuffles, conflict-free LDS).
// Phase 2: combine partials + pe, block max, exp + mask + sums.
// Phase 3: float4 value streaming, 8 warps, unroll 8.
// ---------------------------------------------------------------------------
__global__ __launch_bounds__(256) void attn_split_kernel(const float* __restrict__ key,
                                                         const float* __restrict__ value,
                                                         const float* __restrict__ span) {
    __shared__ float4 Ks4[2][HT * 16];    // 32 KB, XOR-swizzled, double buffer
    __shared__ float4 qs4[16];
    __shared__ float sP[4][CHUNKMAX];     // k-quarter partials; [0]: scores/weights
    __shared__ float wred[8], zr[8], zmr[8];

    int split = blockIdx.x;
    int n = blockIdx.y;
    int t = threadIdx.x, w = t >> 5, lane = t & 31;
    int ps = n * SPLIT + split;

    float spanM = span[n & (NHEADS - 1)] * (float)MLEN;
    int mstart = vis_start(spanM);
    int L = MLEN - mstart;
    int clen = (((L + SPLIT - 1) / SPLIT) + 15) & ~15;
    int a = mstart + split * clen;
    int bend = a + clen;
    if (bend > MLEN) bend = MLEN;

    if (a >= bend) {   // empty split (uniform branch)
        if (t < 64) g_pout[(size_t)ps * HD + t] = 0.f;
        if (t == 64) { g_pmax[ps] = -1e30f; g_pz[ps] = 0.f; g_pzm[ps] = 0.f; }
        return;
    }
    int cnt = bend - a;
    int nht = (cnt + HT - 1) >> 6;

    if (t < 16) qs4[t] = reinterpret_cast<const float4*>(g_q + n * HD)[t];
    const float4* ksrc = reinterpret_cast<const float4*>(key + (size_t)n * MLEN * HD);
    const float* pen = g_pe + (size_t)n * MLEN;
    unsigned int ks_smem = (unsigned int)__cvta_generic_to_shared(&Ks4[0][0]);

    // issue one half-tile's cp.async group (uniform across block)
    auto issue_ht = [&](int h) {
        int gm = a + (h << 6);
        int R = bend - gm; if (R > HT) R = HT;
        unsigned int base = ks_smem + (unsigned int)(h & 1) * (HT * 16 * 16);
#pragma unroll
        for (int j = 0; j < 4; j++) {
            int idx = t + 256 * j;
            int row = idx >> 4, c = idx & 15;
            if (row < R)
                cp_async16(base + (unsigned int)(((row << 4) + (c ^ (row & 15))) * 16),
                           ksrc + (size_t)(gm + row) * 16 + c);
        }
        cp_commit();
    };

    issue_ht(0);
    if (nht > 1) issue_ht(1);

    // ---- Phase 1: pipelined partial dots.  Thread (r, qd) handles 4 c's.
    int r = t & 63, qd = t >> 6;
    for (int h = 0; h < nht; h++) {
        if (h + 1 < nht) asm volatile("cp.async.wait_group 1;\n" ::: "memory");
        else             asm volatile("cp.async.wait_group 0;\n" ::: "memory");
        __syncthreads();
        int gm = a + (h << 6);
        int R = bend - gm; if (R > HT) R = HT;
        float part = 0.f;
        if (r < R) {
            const float4* buf = Ks4[h & 1];
#pragma unroll
            for (int j = 0; j < 4; j++) {
                int c = qd * 4 + j;
                float4 kv = buf[(r << 4) + (c ^ (r & 15))];
                float4 qv = qs4[c];
                part = fmaf(kv.x, qv.x, fmaf(kv.y, qv.y,
                        fmaf(kv.z, qv.z, fmaf(kv.w, qv.w, part))));
            }
        }
        sP[qd][(h << 6) + r] = part;
        __syncthreads();            // buffer free before re-fill
        if (h + 2 < nht) issue_ht(h + 2);
    }

    // ---- Phase 2a: combine partials + pe, block max.
    int padded = nht << 6;
    float lmax = -1e30f;
#pragma unroll 2
    for (int ml = t; ml < padded; ml += 256) {
        float sc = (ml < cnt) ? sP[0][ml] + sP[1][ml] + sP[2][ml] + sP[3][ml]
                                + pen[a + ml]
                              : -1e30f;
        sP[0][ml] = sc;
        lmax = fmaxf(lmax, sc);
    }
#pragma unroll
    for (int off = 16; off > 0; off >>= 1)
        lmax = fmaxf(lmax, __shfl_xor_sync(0xffffffffu, lmax, off));
    if (lane == 0) wred[w] = lmax;
    __syncthreads();
    float bmax = wred[0];
#pragma unroll
    for (int j = 1; j < 8; j++) bmax = fmaxf(bmax, wred[j]);

    // ---- Phase 2b: exp, mask, partial sums (local-max scale).
    float z = 0.f, zm = 0.f;
#pragma unroll 2
    for (int ml = t; ml < padded; ml += 256) {
        int m = a + ml;
        float e = __expf(sP[0][ml] - bmax);   // padded entries -> 0
        float mk = ((float)(m + 1 - MLEN) + spanM) * (1.0f / 32.0f) + 1.0f;
        mk = fminf(fmaxf(mk, 0.f), 1.f);
        float em = e * mk;
        z += e;
        zm += em;
        sP[0][ml] = em;
    }
#pragma unroll
    for (int off = 16; off > 0; off >>= 1) {
        z += __shfl_xor_sync(0xffffffffu, z, off);
        zm += __shfl_xor_sync(0xffffffffu, zm, off);
    }
    if (lane == 0) { zr[w] = z; zmr[w] = zm; }
    __syncthreads();
    float zt = 0.f, zmt = 0.f;
#pragma unroll
    for (int j = 0; j < 8; j++) { zt += zr[j]; zmt += zmr[j]; }

    // ---- Phase 3: partial out.  8 warps, 16-lane split, float4/lane.
    int sl = lane & 15, half = lane >> 4;
    const float4* vb = reinterpret_cast<const float4*>(value + (size_t)n * MLEN * HD +
                                                       (size_t)a * HD);
    float4 acc = make_float4(0.f, 0.f, 0.f, 0.f);
#pragma unroll 8
    for (int i = w * 2 + half; i < cnt; i += 16) {
        float wv = sP[0][i];
        float4 v = vb[(size_t)i * 16 + sl];
        acc.x = fmaf(wv, v.x, acc.x);
        acc.y = fmaf(wv, v.y, acc.y);
        acc.z = fmaf(wv, v.z, acc.z);
        acc.w = fmaf(wv, v.w, acc.w);
    }
    acc.x += __shfl_xor_sync(0xffffffffu, acc.x, 16);
    acc.y += __shfl_xor_sync(0xffffffffu, acc.y, 16);
    acc.z += __shfl_xor_sync(0xffffffffu, acc.z, 16);
    acc.w += __shfl_xor_sync(0xffffffffu, acc.w, 16);
    __syncthreads();   // sP[1] partials fully consumed in 2a; safe to reuse
    if (lane < 16) *reinterpret_cast<float4*>(&sP[1][w * 64 + 4 * sl]) = acc;
    __syncthreads();
    if (t < 64) {
        float s = 0.f;
#pragma unroll
        for (int j = 0; j < 8; j++) s += sP[1][j * 64 + t];
        g_pout[(size_t)ps * HD + t] = s;
    }
    if (t == 64) { g_pmax[ps] = bmax; g_pz[ps] = zt; g_pzm[ps] = zmt; }
}

// ---------------------------------------------------------------------------
// Kernel 4: combine splits + output projection, fused.
// grid (BATCH, 16), 512 threads.  Stage 1: ctx[512] in smem (replicated per
// y-slice; L2-resident reads).  Stage 2: warp -> 2 outputs.
// ---------------------------------------------------------------------------
__global__ __launch_bounds__(512) void oproj_kernel(const float* __restrict__ Wo,
                                                    float* __restrict__ out) {
    __shared__ float xs[HID];
    int b = blockIdx.x;
    {   // stage 1: thread t owns (h = t>>6, d = t&63)
        int h = threadIdx.x >> 6, d = threadIdx.x & 63;
        int n = b * NHEADS + h;
        float gmax = -1e30f;
#pragma unroll
        for (int i = 0; i < SPLIT; i++) gmax = fmaxf(gmax, g_pmax[n * SPLIT + i]);
        float Z = 0.f, Zm = 0.f, o = 0.f;
#pragma unroll
        for (int i = 0; i < SPLIT; i++) {
            float c = __expf(g_pmax[n * SPLIT + i] - gmax);
            Z = fmaf(c, g_pz[n * SPLIT + i], Z);
            Zm = fmaf(c, g_pzm[n * SPLIT + i], Zm);
            o = fmaf(c, g_pout[(size_t)(n * SPLIT + i) * HD + d], o);
        }
        xs[threadIdx.x] = o / (Zm + 1e-8f * Z);
    }
    __syncthreads();
    const float4* xs4 = reinterpret_cast<const float4*>(xs);
    int w = threadIdx.x >> 5, lane = threadIdx.x & 31;
#pragma unroll
    for (int j = 0; j < 2; j++) {
        int o = blockIdx.y * 32 + w * 2 + j;
        const float4* wr = reinterpret_cast<const float4*>(Wo + (size_t)o * HID);
        float acc = 0.f;
#pragma unroll
        for (int s = 0; s < 4; s++) {
            float4 wv = wr[lane + 32 * s];
            float4 xv = xs4[lane + 32 * s];
            acc += wv.x * xv.x + wv.y * xv.y + wv.z * xv.z + wv.w * xv.w;
        }
#pragma unroll
        for (int off = 16; off > 0; off >>= 1)
            acc += __shfl_xor_sync(0xffffffffu, acc, off);
        if (lane == 0) out[b * HID + o] = acc;
    }
}

// ---------------------------------------------------------------------------
extern "C" void kernel_launch(void* const* d_in, const int* in_sizes, int n_in,
                              void* d_out, int out_size) {
    const float* query  = (const float*)d_in[0];
    const float* key    = (const float*)d_in[1];
    const float* value  = (const float*)d_in[2];
    const float* Wq     = (const float*)d_in[3];
    const float* Wo     = (const float*)d_in[4];
    const float* key_pe = (const float*)d_in[5];
    const float* span   = (const float*)d_in[6];
    float* out = (float*)d_out;
    (void)in_sizes; (void)n_in; (void)out_size;

    qproj_kernel<<<dim3(BATCH, 16), 512>>>(query, Wq);
    pe_kernel<<<dim3(MLEN / 64, NTOT / 64), 256>>>(key_pe, span);
    attn_split_kernel<<<dim3(SPLIT, NTOT), 256>>>(key, value, span);
    oproj_kernel<<<dim3(BATCH, 16), 512>>>(Wo, out);
}